// round 4
// baseline (speedup 1.0000x reference)
#include <cuda_runtime.h>

// Problem constants
#define B_ 32
#define L_ 512
#define D_ 512
#define S_ 8

// Scratch: P[b][k][i][e] = arg1[b,i,:] @ Mr[k]   (256 MiB, static device alloc)
__device__ float g_P[(size_t)B_ * S_ * L_ * D_];
// Per-row projections [B*L][S]
__device__ float g_G1[B_ * L_ * S_];
__device__ float g_G2[B_ * L_ * S_];
__device__ float g_S1[B_ * L_ * S_];
__device__ float g_S2[B_ * L_ * S_];

__device__ __forceinline__ float sigmoidf_(float x) {
    // MUFU EX2 + MUFU RCP path, ~2^-22 rel err
    return __fdividef(1.0f, 1.0f + __expf(-x));
}

// ---------------------------------------------------------------------------
// Kernel A: row projections G1,G2,S1,S2  [B*L, 8] each
// grid = B*L blocks, 256 threads (8 warps x 4 dot-products each)
// ---------------------------------------------------------------------------
__global__ __launch_bounds__(256) void proj_kernel(
    const float* __restrict__ arg1, const float* __restrict__ arg2,
    const float* __restrict__ Wg, const float* __restrict__ V) {
    int r = blockIdx.x;  // 0..B*L-1
    __shared__ float row1[D_], row2[D_];
    const float* a1 = arg1 + (size_t)r * D_;
    const float* a2 = arg2 + (size_t)r * D_;
    for (int d = threadIdx.x; d < D_; d += 256) {
        row1[d] = a1[d];
        row2[d] = a2[d];
    }
    __syncthreads();
    int w = threadIdx.x >> 5, lane = threadIdx.x & 31;
#pragma unroll
    for (int q = 0; q < 4; q++) {
        int o = w * 4 + q;      // 0..31
        int p = o >> 3;         // 0:G1 1:G2 2:S1 3:S2
        int s = o & 7;
        const float* W = (p < 2) ? Wg : V;
        const float* row = (p & 1) ? row2 : row1;
        int off = (p & 1) ? D_ : 0;
        float sum = 0.f;
#pragma unroll 4
        for (int d = lane; d < D_; d += 32)
            sum += row[d] * W[(off + d) * S_ + s];
#pragma unroll
        for (int m = 16; m; m >>= 1) sum += __shfl_xor_sync(0xffffffffu, sum, m);
        if (lane == 0) {
            float* dst = (p == 0) ? g_G1 : (p == 1) ? g_G2 : (p == 2) ? g_S1 : g_S2;
            dst[r * S_ + s] = sum;
        }
    }
}

// ---------------------------------------------------------------------------
// Kernel B: P[b,k,i,e] = sum_d arg1[b,i,d] * Mr[k,d,e]
// 8 GEMMs [16384 x 512 x 512]; 64x64x16 tile, 256 threads, 4x4 microtile
// grid = (Ntiles=8, Mtiles=256, k=8)
// ---------------------------------------------------------------------------
__global__ __launch_bounds__(256) void pmul_kernel(
    const float* __restrict__ arg1, const float* __restrict__ Mr) {
    const int k = blockIdx.z;
    const int mB = blockIdx.y;   // 64-row tile over B*L
    const int nB = blockIdx.x;   // 64-col tile over D
    __shared__ float As[16][64];
    __shared__ float Bs[16][64];
    const int tid = threadIdx.x;
    const int tm = tid >> 4, tn = tid & 15;
    float acc[4][4] = {};
    const float* Atile = arg1 + (size_t)mB * 64 * D_;
    const float* Btile = Mr + (size_t)k * D_ * D_ + nB * 64;
    const int mA = tid >> 2, dqA = (tid & 3) * 4;  // A tile load map
    const int dB = tid >> 4, cB = (tid & 15) * 4;  // B tile load map

    for (int d0 = 0; d0 < D_; d0 += 16) {
        float4 va = *(const float4*)(Atile + (size_t)mA * D_ + d0 + dqA);
        float4 vb = *(const float4*)(Btile + (size_t)(d0 + dB) * D_ + cB);
        __syncthreads();
        As[dqA + 0][mA] = va.x; As[dqA + 1][mA] = va.y;
        As[dqA + 2][mA] = va.z; As[dqA + 3][mA] = va.w;
        *(float4*)&Bs[dB][cB] = vb;
        __syncthreads();
#pragma unroll
        for (int kk = 0; kk < 16; kk++) {
            float4 a4 = *(const float4*)&As[kk][tm * 4];
            float4 b4 = *(const float4*)&Bs[kk][tn * 4];
            float a[4] = {a4.x, a4.y, a4.z, a4.w};
            float b[4] = {b4.x, b4.y, b4.z, b4.w};
#pragma unroll
            for (int i = 0; i < 4; i++)
#pragma unroll
                for (int j = 0; j < 4; j++) acc[i][j] += a[i] * b[j];
        }
    }
    const int m0 = mB * 64;
    const int bb = m0 >> 9;      // batch
    const int i0 = m0 & 511;     // row within batch
    float* Pout = g_P + ((size_t)(bb * S_ + k) * L_ + i0) * D_;
#pragma unroll
    for (int i = 0; i < 4; i++) {
        float4 v = make_float4(acc[i][0], acc[i][1], acc[i][2], acc[i][3]);
        *(float4*)&Pout[(size_t)(tm * 4 + i) * D_ + nB * 64 + tn * 4] = v;
    }
}

// ---------------------------------------------------------------------------
// Kernel C: per (b, i-tile, j-tile): loop k, bi_k = P_k @ arg2^T, fused
// gated epilogue, final sigmoid.  64x64 output tile, 256 threads, 4x4 micro.
// grid = (L/64=8, L/64=8, B=32)
// ---------------------------------------------------------------------------
__global__ __launch_bounds__(256) void score_kernel(
    const float* __restrict__ arg2,
    const float* __restrict__ Bg, const float* __restrict__ bvec,
    const float* __restrict__ U, float* __restrict__ out) {
    const int b = blockIdx.z;
    const int i0 = blockIdx.y * 64;
    const int j0 = blockIdx.x * 64;
    __shared__ float As[16][64];
    __shared__ float Bs[16][64];
    __shared__ float G1t[64 * 8], G2t[64 * 8], S1t[64 * 8], S2t[64 * 8];
    const int tid = threadIdx.x;
    const int tm = tid >> 4, tn = tid & 15;

    // stage projection tiles (contiguous copies)
    for (int t = tid; t < 64 * 8; t += 256) {
        G1t[t] = g_G1[(size_t)(b * L_ + i0) * S_ + t];
        G2t[t] = g_G2[(size_t)(b * L_ + j0) * S_ + t];
        S1t[t] = g_S1[(size_t)(b * L_ + i0) * S_ + t];
        S2t[t] = g_S2[(size_t)(b * L_ + j0) * S_ + t];
    }

    float partial[4][4] = {};
    const float* Btile = arg2 + ((size_t)b * L_ + j0) * D_;
    const int mA = tid >> 2, dqA = (tid & 3) * 4;

    for (int k = 0; k < S_; k++) {
        float acc[4][4] = {};
        const float* Atile = g_P + ((size_t)(b * S_ + k) * L_ + i0) * D_;
        for (int e0 = 0; e0 < D_; e0 += 16) {
            float4 va = *(const float4*)(Atile + (size_t)mA * D_ + e0 + dqA);
            float4 vb = *(const float4*)(Btile + (size_t)mA * D_ + e0 + dqA);
            __syncthreads();
            As[dqA + 0][mA] = va.x; As[dqA + 1][mA] = va.y;
            As[dqA + 2][mA] = va.z; As[dqA + 3][mA] = va.w;
            Bs[dqA + 0][mA] = vb.x; Bs[dqA + 1][mA] = vb.y;
            Bs[dqA + 2][mA] = vb.z; Bs[dqA + 3][mA] = vb.w;
            __syncthreads();
#pragma unroll
            for (int kk = 0; kk < 16; kk++) {
                float4 a4 = *(const float4*)&As[kk][tm * 4];
                float4 b4 = *(const float4*)&Bs[kk][tn * 4];
                float a[4] = {a4.x, a4.y, a4.z, a4.w};
                float bb4[4] = {b4.x, b4.y, b4.z, b4.w};
#pragma unroll
                for (int i = 0; i < 4; i++)
#pragma unroll
                    for (int j = 0; j < 4; j++) acc[i][j] += a[i] * bb4[j];
            }
        }
        // fused gating epilogue for this slice k
        float Uk = U[k], Bgk = Bg[k];
#pragma unroll
        for (int ii = 0; ii < 4; ii++) {
            float g1 = G1t[(tm * 4 + ii) * S_ + k];
            float s1 = S1t[(tm * 4 + ii) * S_ + k];
#pragma unroll
            for (int jj = 0; jj < 4; jj++) {
                float g2 = G2t[(tn * 4 + jj) * S_ + k];
                float s2 = S2t[(tn * 4 + jj) * S_ + k];
                float g = sigmoidf_(g1 + g2 + Bgk);
                float si = sigmoidf_(s1 + s2);
                // bi*g + si*(1-g) = g*(bi - si) + si
                partial[ii][jj] += Uk * (g * (acc[ii][jj] - si) + si);
            }
        }
    }

    float c0 = 0.f;
#pragma unroll
    for (int kk = 0; kk < S_; kk++) c0 += U[kk] * bvec[kk];

#pragma unroll
    for (int ii = 0; ii < 4; ii++) {
        int i = i0 + tm * 4 + ii;
        float4 v;
        v.x = sigmoidf_(partial[ii][0] + c0);
        v.y = sigmoidf_(partial[ii][1] + c0);
        v.z = sigmoidf_(partial[ii][2] + c0);
        v.w = sigmoidf_(partial[ii][3] + c0);
        *(float4*)&out[((size_t)b * L_ + i) * L_ + j0 + tn * 4] = v;
    }
}

// ---------------------------------------------------------------------------
extern "C" void kernel_launch(void* const* d_in, const int* in_sizes, int n_in,
                              void* d_out, int out_size) {
    const float* arg1 = (const float*)d_in[0];  // [B,L,D]
    const float* arg2 = (const float*)d_in[1];  // [B,L,D]
    const float* Wg   = (const float*)d_in[2];  // [2D,S]
    const float* Bg   = (const float*)d_in[3];  // [S]
    const float* Mr   = (const float*)d_in[4];  // [S,D,D]
    const float* V    = (const float*)d_in[5];  // [2D,S]
    const float* bvec = (const float*)d_in[6];  // [S]
    const float* U    = (const float*)d_in[7];  // [S]
    float* out = (float*)d_out;                 // [B,L,L]

    (void)in_sizes; (void)n_in; (void)out_size;

    proj_kernel<<<B_ * L_, 256>>>(arg1, arg2, Wg, V);
    pmul_kernel<<<dim3(D_ / 64, (B_ * L_) / 64, S_), 256>>>(arg1, Mr);
    score_kernel<<<dim3(L_ / 64, L_ / 64, B_), 256>>>(arg2, Bg, bvec, U, out);
}

// round 8
// speedup vs baseline: 2.5660x; 2.5660x over previous
#include <cuda_runtime.h>
#include <cuda_bf16.h>
#include <cstdint>

#define B_ 32
#define L_ 512
#define D_ 512
#define S_ 8
#define BL_ (B_ * L_)

// ---------------- static device scratch ----------------
__device__ __nv_bfloat16 g_A1h[(size_t)BL_ * D_];
__device__ __nv_bfloat16 g_A1l[(size_t)BL_ * D_];
__device__ __nv_bfloat16 g_A2h[(size_t)BL_ * D_];
__device__ __nv_bfloat16 g_A2l[(size_t)BL_ * D_];
__device__ __nv_bfloat16 g_Mth[(size_t)S_ * D_ * D_];  // Mr^T [k][e][d]
__device__ __nv_bfloat16 g_Mtl[(size_t)S_ * D_ * D_];
__device__ __nv_bfloat16 g_Ph[(size_t)B_ * S_ * L_ * D_];  // P [b,k,i,e]
__device__ __nv_bfloat16 g_Pl[(size_t)B_ * S_ * L_ * D_];
// factored sigmoid tables: exp(-g1), exp(-(g2+Bg)), exp(-s1), exp(-s2)
__device__ float g_EG1[BL_ * S_], g_EG2[BL_ * S_], g_ES1[BL_ * S_], g_ES2[BL_ * S_];

// ---------------- helpers ----------------
__device__ __forceinline__ uint32_t smem_u32(const void* p) {
    return (uint32_t)__cvta_generic_to_shared(p);
}
__device__ __forceinline__ void ldm_x4(uint32_t* r, uint32_t a) {
    asm volatile("ldmatrix.sync.aligned.m8n8.x4.shared.b16 {%0,%1,%2,%3}, [%4];"
                 : "=r"(r[0]), "=r"(r[1]), "=r"(r[2]), "=r"(r[3]) : "r"(a));
}
__device__ __forceinline__ void ldm_x2(uint32_t* r, uint32_t a) {
    asm volatile("ldmatrix.sync.aligned.m8n8.x2.shared.b16 {%0,%1}, [%2];"
                 : "=r"(r[0]), "=r"(r[1]) : "r"(a));
}
__device__ __forceinline__ void mma_bf16(float* d, const uint32_t* a, const uint32_t* b) {
    asm volatile(
        "mma.sync.aligned.m16n8k16.row.col.f32.bf16.bf16.f32 "
        "{%0,%1,%2,%3},{%4,%5,%6,%7},{%8,%9},{%0,%1,%2,%3};"
        : "+f"(d[0]), "+f"(d[1]), "+f"(d[2]), "+f"(d[3])
        : "r"(a[0]), "r"(a[1]), "r"(a[2]), "r"(a[3]), "r"(b[0]), "r"(b[1]));
}
__device__ __forceinline__ void cp16(uint32_t dst, const void* src) {
    asm volatile("cp.async.cg.shared.global [%0], [%1], 16;" ::"r"(dst), "l"(src));
}
#define CP_COMMIT() asm volatile("cp.async.commit_group;" ::: "memory")
#define CP_WAIT1() asm volatile("cp.async.wait_group 1;" ::: "memory")
#define CP_WAIT0() asm volatile("cp.async.wait_group 0;" ::: "memory")

// Newton reciprocal (no MUFU): a >= 1 here.
__device__ __forceinline__ float rcp_nr(float a) {
    float r = __uint_as_float(0x7EF311C3u - __float_as_uint(a));
    r = r * fmaf(-a, r, 2.0f);
    r = r * fmaf(-a, r, 2.0f);
    r = r * fmaf(-a, r, 2.0f);
    return r;
}
__device__ __forceinline__ float nexp(float x) {  // exp(-clamp(x, +/-40))
    x = fminf(fmaxf(x, -40.f), 40.f);
    return expf(-x);
}
__device__ __forceinline__ uint32_t pack_bf2(float f0, float f1,
                                             uint32_t& lopack) {
    __nv_bfloat16 h0 = __float2bfloat16(f0), h1 = __float2bfloat16(f1);
    __nv_bfloat16 l0 = __float2bfloat16(f0 - __bfloat162float(h0));
    __nv_bfloat16 l1 = __float2bfloat16(f1 - __bfloat162float(h1));
    lopack = (uint32_t)__bfloat16_as_ushort(l0) |
             ((uint32_t)__bfloat16_as_ushort(l1) << 16);
    return (uint32_t)__bfloat16_as_ushort(h0) |
           ((uint32_t)__bfloat16_as_ushort(h1) << 16);
}

// ---------------------------------------------------------------------------
// Kernel 1: projections -> exp tables, plus fp32->bf16(hi,lo) of arg1/arg2.
// grid = BL/8, 256 threads (warp per row). dyn smem 64KB.
// ---------------------------------------------------------------------------
__global__ __launch_bounds__(256) void proj_convert(
    const float* __restrict__ arg1, const float* __restrict__ arg2,
    const float* __restrict__ Wg, const float* __restrict__ V,
    const float* __restrict__ Bg) {
    extern __shared__ float wsm[];  // [0:8192) Wg^T [s][1024], [8192:16384) V^T
    for (int t = threadIdx.x; t < 8192; t += 256) {
        int d = t >> 3, s = t & 7;
        wsm[s * 1024 + d] = Wg[t];
        wsm[8192 + s * 1024 + d] = V[t];
    }
    __syncthreads();
    int w = threadIdx.x >> 5, lane = threadIdx.x & 31;
    int r = blockIdx.x * 8 + w;
    const float* a1 = arg1 + (size_t)r * D_;
    const float* a2 = arg2 + (size_t)r * D_;
    float aG1[8] = {}, aG2[8] = {}, aS1[8] = {}, aS2[8] = {};
#pragma unroll
    for (int t = 0; t < 16; t++) {
        int d = lane + t * 32;
        float v1 = a1[d], v2 = a2[d];
        __nv_bfloat16 h1 = __float2bfloat16(v1);
        g_A1h[(size_t)r * D_ + d] = h1;
        g_A1l[(size_t)r * D_ + d] = __float2bfloat16(v1 - __bfloat162float(h1));
        __nv_bfloat16 h2 = __float2bfloat16(v2);
        g_A2h[(size_t)r * D_ + d] = h2;
        g_A2l[(size_t)r * D_ + d] = __float2bfloat16(v2 - __bfloat162float(h2));
#pragma unroll
        for (int s = 0; s < 8; s++) {
            aG1[s] += v1 * wsm[s * 1024 + d];
            aG2[s] += v2 * wsm[s * 1024 + 512 + d];
            aS1[s] += v1 * wsm[8192 + s * 1024 + d];
            aS2[s] += v2 * wsm[8192 + s * 1024 + 512 + d];
        }
    }
#pragma unroll
    for (int m = 16; m; m >>= 1) {
#pragma unroll
        for (int s = 0; s < 8; s++) {
            aG1[s] += __shfl_xor_sync(0xffffffffu, aG1[s], m);
            aG2[s] += __shfl_xor_sync(0xffffffffu, aG2[s], m);
            aS1[s] += __shfl_xor_sync(0xffffffffu, aS1[s], m);
            aS2[s] += __shfl_xor_sync(0xffffffffu, aS2[s], m);
        }
    }
    if (lane == 0) {
#pragma unroll
        for (int s = 0; s < 8; s++) {
            g_EG1[r * 8 + s] = nexp(aG1[s]);
            g_EG2[r * 8 + s] = nexp(aG2[s] + Bg[s]);
            g_ES1[r * 8 + s] = nexp(aS1[s]);
            g_ES2[r * 8 + s] = nexp(aS2[s]);
        }
    }
}

// ---------------------------------------------------------------------------
// Kernel 2: Mr [k,d,e] -> transposed bf16 split Mt [k,e,d].
// ---------------------------------------------------------------------------
__global__ void mr_transpose(const float* __restrict__ Mr) {
    __shared__ float tile[32][33];
    int k = blockIdx.z;
    int d0 = blockIdx.y * 32, e0 = blockIdx.x * 32;
    const float* src = Mr + (size_t)k * D_ * D_;
    for (int rr = threadIdx.y; rr < 32; rr += 8)
        tile[rr][threadIdx.x] = src[(size_t)(d0 + rr) * D_ + e0 + threadIdx.x];
    __syncthreads();
    __nv_bfloat16* dh = g_Mth + (size_t)k * D_ * D_;
    __nv_bfloat16* dl = g_Mtl + (size_t)k * D_ * D_;
    for (int rr = threadIdx.y; rr < 32; rr += 8) {
        float v = tile[threadIdx.x][rr];
        __nv_bfloat16 h = __float2bfloat16(v);
        dh[(size_t)(e0 + rr) * D_ + d0 + threadIdx.x] = h;
        dl[(size_t)(e0 + rr) * D_ + d0 + threadIdx.x] =
            __float2bfloat16(v - __bfloat162float(h));
    }
}

// ---------------------------------------------------------------------------
// Kernel 3: P = arg1 @ Mr^T  (split-bf16, 3 mma passes), CTA 128x128, BK=32.
// 8 warps as 2(M=64) x 4(N=32). cp.async double-buffered pipeline.
// smem: per stage [Ah|Al|Bh|Bl] each 128x(32 pad 40) bf16 = 10240B -> 40960/stage.
// grid = (4, 128, 8)
// ---------------------------------------------------------------------------
__global__ __launch_bounds__(256, 1) void pmul_mma() {
    const int k = blockIdx.z, mB = blockIdx.y, nB = blockIdx.x;
    extern __shared__ char sm[];
    const uint32_t sb = smem_u32(sm);
    const int tid = threadIdx.x, wid = tid >> 5, lane = tid & 31;
    const int warpM = wid >> 2, warpN = wid & 3;

    const __nv_bfloat16* pAh = g_A1h + (size_t)mB * 128 * D_;
    const __nv_bfloat16* pAl = g_A1l + (size_t)mB * 128 * D_;
    const __nv_bfloat16* pBh = g_Mth + ((size_t)k * D_ + nB * 128) * D_;
    const __nv_bfloat16* pBl = g_Mtl + ((size_t)k * D_ + nB * 128) * D_;

    auto load_chunk = [&](int c, int buf) {
        uint32_t dstb = sb + (uint32_t)buf * 40960u;
#pragma unroll
        for (int rr = 0; rr < 2; rr++) {
            int op = tid + rr * 256;
            int row = op >> 2, seg = op & 3;
            uint32_t off = (uint32_t)(row * 80 + seg * 16);
            size_t gi = (size_t)row * D_ + c * 32 + seg * 8;
            cp16(dstb + off, pAh + gi);
            cp16(dstb + 10240u + off, pAl + gi);
            cp16(dstb + 20480u + off, pBh + gi);
            cp16(dstb + 30720u + off, pBl + gi);
        }
    };

    float acc[4][4][4];
#pragma unroll
    for (int mt = 0; mt < 4; mt++)
#pragma unroll
        for (int nt = 0; nt < 4; nt++)
#pragma unroll
            for (int q = 0; q < 4; q++) acc[mt][nt][q] = 0.f;

    load_chunk(0, 0);
    CP_COMMIT();
    const int lm = lane & 15, lk = lane >> 4;
    const int bn = lane & 7, bk2 = (lane >> 3) & 1;

    for (int c = 0; c < 16; c++) {
        int buf = c & 1;
        if (c + 1 < 16) { load_chunk(c + 1, buf ^ 1); CP_COMMIT(); CP_WAIT1(); }
        else CP_WAIT0();
        __syncthreads();
        uint32_t sbuf = sb + (uint32_t)buf * 40960u;
#pragma unroll
        for (int ks = 0; ks < 2; ks++) {
            uint32_t ah[4][4], al[4][4], bh[4][2], bl[4][2];
#pragma unroll
            for (int mt = 0; mt < 4; mt++) {
                uint32_t a = sbuf + (uint32_t)((warpM * 64 + mt * 16 + lm) * 80 +
                                               (ks * 16 + lk * 8) * 2);
                ldm_x4(ah[mt], a);
                ldm_x4(al[mt], a + 10240u);
            }
#pragma unroll
            for (int nt = 0; nt < 4; nt++) {
                uint32_t a = sbuf + 20480u +
                             (uint32_t)((warpN * 32 + nt * 8 + bn) * 80 +
                                        (ks * 16 + bk2 * 8) * 2);
                ldm_x2(bh[nt], a);
                ldm_x2(bl[nt], a + 10240u);
            }
#pragma unroll
            for (int mt = 0; mt < 4; mt++)
#pragma unroll
                for (int nt = 0; nt < 4; nt++) {
                    mma_bf16(acc[mt][nt], ah[mt], bh[nt]);
                    mma_bf16(acc[mt][nt], ah[mt], bl[nt]);
                    mma_bf16(acc[mt][nt], al[mt], bh[nt]);
                }
        }
        __syncthreads();
    }

    // epilogue: split to bf16 hi/lo and store P
    const int rowg0 = mB * 128 + warpM * 64;
#pragma unroll
    for (int mt = 0; mt < 4; mt++) {
#pragma unroll
        for (int half = 0; half < 2; half++) {
            int rowg = rowg0 + mt * 16 + (lane >> 2) + half * 8;
            int bb = rowg >> 9, ii = rowg & 511;
            size_t base = ((size_t)(bb * S_ + k) * L_ + ii) * D_ + nB * 128;
#pragma unroll
            for (int nt = 0; nt < 4; nt++) {
                int colg = warpN * 32 + nt * 8 + (lane & 3) * 2;
                uint32_t wl;
                uint32_t wh = pack_bf2(acc[mt][nt][half * 2],
                                       acc[mt][nt][half * 2 + 1], wl);
                *(uint32_t*)(g_Ph + base + colg) = wh;
                *(uint32_t*)(g_Pl + base + colg) = wl;
            }
        }
    }
}

// ---------------------------------------------------------------------------
// Kernel 4: per (b, i-tile 128, j-tile 64): loop k, bi = P @ arg2^T (split-bf16)
// + fused factored-sigmoid gating (Newton recip, no MUFU), final sigmoid.
// 8 warps as 2(M=64) x 4(N=16). smem: 2 stages x [Ah 10240|Al 10240|Bh 5120|
// Bl 5120] = 30720/stage; exp tables at 61440.
// grid = (8, 4, 32)
// ---------------------------------------------------------------------------
__global__ __launch_bounds__(256, 1) void score_mma(
    const float* __restrict__ U, const float* __restrict__ bvec,
    float* __restrict__ out) {
    const int b = blockIdx.z;
    const int i0 = blockIdx.y * 128;
    const int j0 = blockIdx.x * 64;
    extern __shared__ char sm[];
    const uint32_t sb = smem_u32(sm);
    float* EG1t = (float*)(sm + 61440);  // [128][9]
    float* ES1t = (float*)(sm + 66048);  // [128][9]
    float* EG2t = (float*)(sm + 70656);  // [8][64]
    float* ES2t = (float*)(sm + 72704);  // [8][64]
    const int tid = threadIdx.x, wid = tid >> 5, lane = tid & 31;
    const int warpM = wid >> 2, warpN = wid & 3;

    for (int t = tid; t < 1024; t += 256) {
        int r = t >> 3, s = t & 7;
        EG1t[r * 9 + s] = g_EG1[(size_t)(b * L_ + i0 + r) * 8 + s];
        ES1t[r * 9 + s] = g_ES1[(size_t)(b * L_ + i0 + r) * 8 + s];
    }
    for (int t = tid; t < 512; t += 256) {
        int kk = t >> 6, j = t & 63;
        EG2t[kk * 64 + j] = g_EG2[(size_t)(b * L_ + j0 + j) * 8 + kk];
        ES2t[kk * 64 + j] = g_ES2[(size_t)(b * L_ + j0 + j) * 8 + kk];
    }

    float Ur[8];
#pragma unroll
    for (int s = 0; s < 8; s++) Ur[s] = __ldg(U + s);
    float c0 = 0.f;
#pragma unroll
    for (int s = 0; s < 8; s++) c0 += Ur[s] * __ldg(bvec + s);

    const __nv_bfloat16* pBh = g_A2h + (size_t)(b * L_ + j0) * D_;
    const __nv_bfloat16* pBl = g_A2l + (size_t)(b * L_ + j0) * D_;

    auto load_chunk = [&](int cc, int buf) {
        int k = cc >> 4, c = cc & 15;
        const __nv_bfloat16* pAh = g_Ph + ((size_t)(b * S_ + k) * L_ + i0) * D_;
        const __nv_bfloat16* pAl = g_Pl + ((size_t)(b * S_ + k) * L_ + i0) * D_;
        uint32_t dstb = sb + (uint32_t)buf * 30720u;
#pragma unroll
        for (int rr = 0; rr < 2; rr++) {
            int op = tid + rr * 256;
            int row = op >> 2, seg = op & 3;
            uint32_t off = (uint32_t)(row * 80 + seg * 16);
            size_t gi = (size_t)row * D_ + c * 32 + seg * 8;
            cp16(dstb + off, pAh + gi);
            cp16(dstb + 10240u + off, pAl + gi);
        }
        {
            int row = tid >> 2, seg = tid & 3;
            uint32_t off = (uint32_t)(row * 80 + seg * 16);
            size_t gi = (size_t)row * D_ + c * 32 + seg * 8;
            cp16(dstb + 20480u + off, pBh + gi);
            cp16(dstb + 25600u + off, pBl + gi);
        }
    };

    float acc[4][2][4], part[4][2][4];
#pragma unroll
    for (int mt = 0; mt < 4; mt++)
#pragma unroll
        for (int nt = 0; nt < 2; nt++)
#pragma unroll
            for (int q = 0; q < 4; q++) part[mt][nt][q] = 0.f;

    load_chunk(0, 0);
    CP_COMMIT();
    const int lm = lane & 15, lk = lane >> 4;
    const int bn = lane & 7, bk2 = (lane >> 3) & 1;

    for (int cc = 0; cc < 128; cc++) {
        int k = cc >> 4, c = cc & 15, buf = cc & 1;
        if (cc + 1 < 128) { load_chunk(cc + 1, buf ^ 1); CP_COMMIT(); CP_WAIT1(); }
        else CP_WAIT0();
        __syncthreads();
        if (c == 0) {
#pragma unroll
            for (int mt = 0; mt < 4; mt++)
#pragma unroll
                for (int nt = 0; nt < 2; nt++)
#pragma unroll
                    for (int q = 0; q < 4; q++) acc[mt][nt][q] = 0.f;
        }
        uint32_t sbuf = sb + (uint32_t)buf * 30720u;
#pragma unroll
        for (int ks = 0; ks < 2; ks++) {
            uint32_t ah[4][4], al[4][4], bh[2][2], bl[2][2];
#pragma unroll
            for (int mt = 0; mt < 4; mt++) {
                uint32_t a = sbuf + (uint32_t)((warpM * 64 + mt * 16 + lm) * 80 +
                                               (ks * 16 + lk * 8) * 2);
                ldm_x4(ah[mt], a);
                ldm_x4(al[mt], a + 10240u);
            }
#pragma unroll
            for (int nt = 0; nt < 2; nt++) {
                uint32_t a = sbuf + 20480u +
                             (uint32_t)((warpN * 16 + nt * 8 + bn) * 80 +
                                        (ks * 16 + bk2 * 8) * 2);
                ldm_x2(bh[nt], a);
                ldm_x2(bl[nt], a + 5120u);
            }
#pragma unroll
            for (int mt = 0; mt < 4; mt++)
#pragma unroll
                for (int nt = 0; nt < 2; nt++) {
                    mma_bf16(acc[mt][nt], ah[mt], bh[nt]);
                    mma_bf16(acc[mt][nt], ah[mt], bl[nt]);
                    mma_bf16(acc[mt][nt], al[mt], bh[nt]);
                }
        }
        if (c == 15) {
            float Uk = Ur[k];
#pragma unroll
            for (int mt = 0; mt < 4; mt++) {
                int r0 = warpM * 64 + mt * 16 + (lane >> 2);
                float eg1a = EG1t[r0 * 9 + k], es1a = ES1t[r0 * 9 + k];
                float eg1b = EG1t[(r0 + 8) * 9 + k], es1b = ES1t[(r0 + 8) * 9 + k];
#pragma unroll
                for (int nt = 0; nt < 2; nt++) {
                    int jj = warpN * 16 + nt * 8 + (lane & 3) * 2;
                    float eg2x = EG2t[k * 64 + jj], eg2y = EG2t[k * 64 + jj + 1];
                    float es2x = ES2t[k * 64 + jj], es2y = ES2t[k * 64 + jj + 1];
                    float g, s;
                    g = rcp_nr(fmaf(eg1a, eg2x, 1.f));
                    s = rcp_nr(fmaf(es1a, es2x, 1.f));
                    part[mt][nt][0] =
                        fmaf(Uk, fmaf(g, acc[mt][nt][0] - s, s), part[mt][nt][0]);
                    g = rcp_nr(fmaf(eg1a, eg2y, 1.f));
                    s = rcp_nr(fmaf(es1a, es2y, 1.f));
                    part[mt][nt][1] =
                        fmaf(Uk, fmaf(g, acc[mt][nt][1] - s, s), part[mt][nt][1]);
                    g = rcp_nr(fmaf(eg1b, eg2x, 1.f));
                    s = rcp_nr(fmaf(es1b, es2x, 1.f));
                    part[mt][nt][2] =
                        fmaf(Uk, fmaf(g, acc[mt][nt][2] - s, s), part[mt][nt][2]);
                    g = rcp_nr(fmaf(eg1b, eg2y, 1.f));
                    s = rcp_nr(fmaf(es1b, es2y, 1.f));
                    part[mt][nt][3] =
                        fmaf(Uk, fmaf(g, acc[mt][nt][3] - s, s), part[mt][nt][3]);
                }
            }
        }
        __syncthreads();
    }

    // final sigmoid + store
#pragma unroll
    for (int mt = 0; mt < 4; mt++) {
        int ibase = i0 + warpM * 64 + mt * 16 + (lane >> 2);
#pragma unroll
        for (int half = 0; half < 2; half++) {
            float* orow = out + ((size_t)b * L_ + ibase + half * 8) * L_ + j0;
#pragma unroll
            for (int nt = 0; nt < 2; nt++) {
                int jj = warpN * 16 + nt * 8 + (lane & 3) * 2;
                float z0 = part[mt][nt][half * 2 + 0] + c0;
                float z1 = part[mt][nt][half * 2 + 1] + c0;
                float2 v;
                v.x = rcp_nr(1.f + __expf(-z0));
                v.y = rcp_nr(1.f + __expf(-z1));
                *(float2*)(orow + jj) = v;
            }
        }
    }
}

// ---------------------------------------------------------------------------
extern "C" void kernel_launch(void* const* d_in, const int* in_sizes, int n_in,
                              void* d_out, int out_size) {
    const float* arg1 = (const float*)d_in[0];
    const float* arg2 = (const float*)d_in[1];
    const float* Wg   = (const float*)d_in[2];
    const float* Bg   = (const float*)d_in[3];
    const float* Mr   = (const float*)d_in[4];
    const float* V    = (const float*)d_in[5];
    const float* bvec = (const float*)d_in[6];
    const float* U    = (const float*)d_in[7];
    float* out = (float*)d_out;
    (void)in_sizes; (void)n_in; (void)out_size;

    const int SMEM_PROJ = 65536;
    const int SMEM_B = 81920;
    const int SMEM_C = 74752;
    cudaFuncSetAttribute(proj_convert, cudaFuncAttributeMaxDynamicSharedMemorySize, SMEM_PROJ);
    cudaFuncSetAttribute(pmul_mma, cudaFuncAttributeMaxDynamicSharedMemorySize, SMEM_B);
    cudaFuncSetAttribute(score_mma, cudaFuncAttributeMaxDynamicSharedMemorySize, SMEM_C);

    proj_convert<<<BL_ / 8, 256, SMEM_PROJ>>>(arg1, arg2, Wg, V, Bg);
    mr_transpose<<<dim3(16, 16, 8), dim3(32, 8)>>>(Mr);
    pmul_mma<<<dim3(4, 128, 8), 256, SMEM_B>>>();
    score_mma<<<dim3(8, 4, 32), 256, SMEM_C>>>(U, bvec, out);
}